// round 15
// baseline (speedup 1.0000x reference)
#include <cuda_runtime.h>
#include <cuda_fp16.h>
#include <cstdint>

#define N_NODES  50000
#define N_EDGES  800000
#define BM       64
#define THREADS  256
#define ASTR     576     // A row stride bytes: 16B-aligned; /4=144 ≡16 mod 32 -> conflict-free LDS.128

// ---------------- device scratch (no allocs allowed; zero-initialized at load) ----
__device__ float  g_agg[N_NODES * 64];
__device__ __half g_w1h[256 * 256];
__device__ __half g_w2h[256 * 256];
__device__ __half g_w3h[256 * 128];

// ---------------- helpers ----------------
__device__ __forceinline__ void cp16(uint32_t smem_dst, const void* gsrc) {
    asm volatile("cp.async.cg.shared.global [%0], [%1], 16;" :: "r"(smem_dst), "l"(gsrc));
}
__device__ __forceinline__ uint4 lds128(uint32_t addr) {
    uint4 r;
    asm volatile("ld.shared.v4.b32 {%0,%1,%2,%3}, [%4];"
                 : "=r"(r.x), "=r"(r.y), "=r"(r.z), "=r"(r.w) : "r"(addr));
    return r;
}
__device__ __forceinline__ void mma_f16(float* c, uint32_t a0, uint32_t a1, uint32_t a2,
                                        uint32_t a3, uint32_t b0, uint32_t b1) {
    asm volatile(
        "mma.sync.aligned.m16n8k16.row.col.f32.f16.f16.f32 "
        "{%0,%1,%2,%3}, {%4,%5,%6,%7}, {%8,%9}, {%0,%1,%2,%3};"
        : "+f"(c[0]), "+f"(c[1]), "+f"(c[2]), "+f"(c[3])
        : "r"(a0), "r"(a1), "r"(a2), "r"(a3), "r"(b0), "r"(b1));
}
// store half2 into interleaved A layout at logical col c (even)
__device__ __forceinline__ void sts_h2(uint32_t a_u32, int row, int c, float f0, float f1) {
    int w = c & 31;
    int t = (w & 7) >> 1, s = (w >> 3) & 1, q = (w >> 4) & 1;
    uint32_t byte = (uint32_t)(row * ASTR + (c >> 5) * 64 + (8 * t + 4 * q + 2 * s) * 2);
    __half2 h = __floats2half2_rn(f0, f1);
    asm volatile("st.shared.b32 [%0], %1;" :: "r"(a_u32 + byte), "r"(*(uint32_t*)&h));
}

// ---------------- weight permute: gmem image in per-fragment order (fp16) ----
__device__ __forceinline__ void permute_h(const float* __restrict__ W, __half* __restrict__ dst,
                                          int i, int N) {
    int chunk = i / (16 * N);
    int r = i - chunk * 16 * N;
    int wn = r / (4 * N);
    int r2 = r - wn * 4 * N;
    int p = r2 >> 8;
    int lane = (r2 >> 3) & 31;
    int j8 = r2 & 7;
    int g = lane >> 2, t = lane & 3;
    int ni = 2 * p + (j8 >> 2);
    int k = chunk * 16 + 2 * t + 8 * ((j8 >> 1) & 1) + (j8 & 1);
    int n = wn * (N / 4) + ni * 8 + g;
    dst[i] = __float2half_rn(W[(size_t)k * N + n]);
}

// ---------------- scatter (warp-autonomous, pipelined within 32KB) + permute ---
#define SCAT_BLOCKS (N_EDGES / 128)   // 6250
__global__ __launch_bounds__(256) void scatter_prep_kernel(
    const float* __restrict__ edge_attr, const int* __restrict__ col,
    const float* __restrict__ w1, const float* __restrict__ w2,
    const float* __restrict__ w3) {
    int b = blockIdx.x;
    if (b < SCAT_BLOCKS) {
        __shared__ float se[128 * 64];   // 32KB
        const int tid = threadIdx.x, lane = tid & 31, warp = tid >> 5;
        const long e0 = (long)b * 128 + warp * 16;   // this warp's 16 edges
        const float* src = edge_attr + e0 * 64;
        const uint32_t sb = (uint32_t)__cvta_generic_to_shared(se) + warp * 4096;

        int mynode = (lane < 16) ? __ldg(col + e0 + lane) : 0;

        // stage group A: edges [0,8)
#pragma unroll
        for (int j = 0; j < 4; j++)
            cp16(sb + (j * 32 + lane) * 16, src + (j * 32 + lane) * 4);
        asm volatile("cp.async.commit_group;");
        // stage group B: edges [8,16)
#pragma unroll
        for (int j = 0; j < 4; j++)
            cp16(sb + 2048 + (j * 32 + lane) * 16, src + 512 + (j * 32 + lane) * 4);
        asm volatile("cp.async.commit_group;");

        const int eo = lane >> 1, half = lane & 1;
        int node_a = __shfl_sync(0xFFFFFFFF, mynode, eo);
        int node_b = __shfl_sync(0xFFFFFFFF, mynode, 8 + eo);

        asm volatile("cp.async.wait_group 1;");
        __syncwarp();
        asm volatile("fence.proxy.async.shared::cta;" ::: "memory");
        if (lane < 16) {
            asm volatile("cp.reduce.async.bulk.global.shared::cta.bulk_group.add.f32 [%0], [%1], %2;"
                         :: "l"(g_agg + (size_t)node_a * 64 + half * 32),
                            "r"(sb + eo * 256 + half * 128), "r"(128) : "memory");
        }
        asm volatile("cp.async.bulk.commit_group;");

        asm volatile("cp.async.wait_group 0;");
        __syncwarp();
        asm volatile("fence.proxy.async.shared::cta;" ::: "memory");
        if (lane < 16) {
            asm volatile("cp.reduce.async.bulk.global.shared::cta.bulk_group.add.f32 [%0], [%1], %2;"
                         :: "l"(g_agg + (size_t)node_b * 64 + half * 32),
                            "r"(sb + 2048 + eo * 256 + half * 128), "r"(128) : "memory");
        }
        asm volatile("cp.async.bulk.commit_group;");
        asm volatile("cp.async.bulk.wait_group 0;");
    } else {
        int i = (b - SCAT_BLOCKS) * 256 + threadIdx.x;   // 640 blocks -> 163840
        if (i < 65536)        permute_h(w1, g_w1h, i, 256);
        else if (i < 131072)  permute_h(w2, g_w2h, i - 65536, 256);
        else                  permute_h(w3, g_w3h, i - 131072, 128);
    }
}

// ---------------- fused MLP layer, fp16 m16n8k16 --------------------------------
// B fragments: direct gmem(L2/L1)->register LDG.128 with an explicit 2-deep
// rotating prefetch buffer (bvb[2][NP]) so every load is issued ~2 k-chunks
// (>=220 cyc) before its MMAs consume it.
template <int N, bool RELU, bool TOGMEM>
__device__ __forceinline__ void mlp_layer(
    uint32_t a_u32, const __half* __restrict__ Wg,
    const float* __restrict__ bias, float* __restrict__ outg, int m0,
    int wm, int wn, int g, int t, int lane)
{
    constexpr int TW = N / 4;
    constexpr int NI = N / 32;
    constexpr int NP = NI / 2;
    constexpr int CHUNK4 = (16 * N) / 8;   // uint4 per 16-k chunk (all warps): 512 / 256
    constexpr int SLICEH = 4 * N;          // halves per warp slice per chunk

    float acc[2][NI][4] = {};
    const uint4* wptr = reinterpret_cast<const uint4*>(Wg + wn * SLICEH + lane * 8);

    // prime 2-deep B prefetch buffer
    uint4 bvb[2][NP];
#pragma unroll
    for (int p = 0; p < NP; p++) bvb[0][p] = __ldg(wptr + 0 * CHUNK4 + p * 32);
#pragma unroll
    for (int p = 0; p < NP; p++) bvb[1][p] = __ldg(wptr + 1 * CHUNK4 + p * 32);

    uint4 av[2][2];
    const uint32_t arow = a_u32 + (uint32_t)((wm * 32 + g) * ASTR + t * 16);

#pragma unroll
    for (int kt = 0; kt < 16; kt++) {
        const int q = kt & 1;
        if (q == 0) {
#pragma unroll
            for (int mi = 0; mi < 2; mi++)
#pragma unroll
                for (int rh = 0; rh < 2; rh++)
                    av[mi][rh] = lds128(arow + (mi * 16 + rh * 8) * ASTR + (kt >> 1) * 64);
        }
        uint32_t a0[2], a1[2], a2[2], a3[2];
#pragma unroll
        for (int mi = 0; mi < 2; mi++) {
            a0[mi] = q ? av[mi][0].z : av[mi][0].x;
            a1[mi] = q ? av[mi][1].z : av[mi][1].x;
            a2[mi] = q ? av[mi][0].w : av[mi][0].y;
            a3[mi] = q ? av[mi][1].w : av[mi][1].y;
        }
#pragma unroll
        for (int p = 0; p < NP; p++) {
            uint4 bv = bvb[q][p];
            mma_f16(acc[0][2 * p],     a0[0], a1[0], a2[0], a3[0], bv.x, bv.y);
            mma_f16(acc[1][2 * p],     a0[1], a1[1], a2[1], a3[1], bv.x, bv.y);
            mma_f16(acc[0][2 * p + 1], a0[0], a1[0], a2[0], a3[0], bv.z, bv.w);
            mma_f16(acc[1][2 * p + 1], a0[1], a1[1], a2[1], a3[1], bv.z, bv.w);
        }
        // refill this slot for kt+2 (issued after consumption; renamed under unroll)
        if (kt + 2 < 16) {
#pragma unroll
            for (int p = 0; p < NP; p++)
                bvb[q][p] = __ldg(wptr + (kt + 2) * CHUNK4 + p * 32);
        }
    }
    __syncthreads();  // all warps done reading A before epilogue rewrites it

#pragma unroll
    for (int mi = 0; mi < 2; mi++) {
#pragma unroll
        for (int ni = 0; ni < NI; ni++) {
            int c = wn * TW + ni * 8 + 2 * t;
            float bv0 = bias[c], bv1 = bias[c + 1];
            float v0 = acc[mi][ni][0] + bv0;
            float v1 = acc[mi][ni][1] + bv1;
            float v2 = acc[mi][ni][2] + bv0;
            float v3 = acc[mi][ni][3] + bv1;
            if (RELU) {
                v0 = (v0 >= 0.f) ? v0 : 0.01f * v0;
                v1 = (v1 >= 0.f) ? v1 : 0.01f * v1;
                v2 = (v2 >= 0.f) ? v2 : 0.01f * v2;
                v3 = (v3 >= 0.f) ? v3 : 0.01f * v3;
            }
            int row = wm * 32 + mi * 16 + g;
            if (TOGMEM) {
                int gm0 = m0 + row, gm1 = gm0 + 8;
                if (gm0 < N_NODES)
                    *reinterpret_cast<float2*>(outg + (size_t)gm0 * N + c) = make_float2(v0, v1);
                if (gm1 < N_NODES)
                    *reinterpret_cast<float2*>(outg + (size_t)gm1 * N + c) = make_float2(v2, v3);
            } else {
                sts_h2(a_u32, row,     c, v0, v1);
                sts_h2(a_u32, row + 8, c, v2, v3);
            }
        }
    }
    if (!TOGMEM) __syncthreads();
}

// ---------------- fused kernel: h0 build + re-zero agg + 3 layers --------------
__global__ __launch_bounds__(THREADS, 2) void fused_mlp_kernel(
    const float* __restrict__ x, const float* __restrict__ u,
    const int* __restrict__ batch,
    const float* __restrict__ b1, const float* __restrict__ b2,
    const float* __restrict__ b3, float* __restrict__ out) {
    extern __shared__ char smem_raw[];
    __shared__ int s_batch[BM];

    const int tid = threadIdx.x, lane = tid & 31, warp = tid >> 5;
    const int wm = warp & 1, wn = warp >> 1;
    const int g = lane >> 2, t = lane & 3;
    const int m0 = blockIdx.x * BM;

    const uint32_t a_u32 = (uint32_t)__cvta_generic_to_shared(smem_raw);

    if (tid < BM) {
        int gm = m0 + tid;
        s_batch[tid] = (gm < N_NODES) ? batch[gm] : 0;
    }
    // h0 cols [0,128): x  (2048 float4)
#pragma unroll
    for (int i = 0; i < 8; i++) {
        int idx = tid + i * THREADS;
        int row = idx >> 5, c4 = idx & 31;
        int gm = m0 + row;
        float4 v = make_float4(0.f, 0.f, 0.f, 0.f);
        if (gm < N_NODES) v = *reinterpret_cast<const float4*>(x + (size_t)gm * 128 + c4 * 4);
        sts_h2(a_u32, row, 4 * c4,     v.x, v.y);
        sts_h2(a_u32, row, 4 * c4 + 2, v.z, v.w);
    }
    // h0 cols [128,192): agg  (1024 float4)
#pragma unroll
    for (int i = 0; i < 4; i++) {
        int idx = tid + i * THREADS;
        int row = idx >> 4, c4 = idx & 15;
        int gm = m0 + row;
        float4 v = make_float4(0.f, 0.f, 0.f, 0.f);
        if (gm < N_NODES) v = *reinterpret_cast<const float4*>(g_agg + (size_t)gm * 64 + c4 * 4);
        sts_h2(a_u32, row, 128 + 4 * c4,     v.x, v.y);
        sts_h2(a_u32, row, 128 + 4 * c4 + 2, v.z, v.w);
    }
    __syncthreads();  // s_batch ready
    // h0 cols [192,256): u[batch]  (1024 float4)
#pragma unroll
    for (int i = 0; i < 4; i++) {
        int idx = tid + i * THREADS;
        int row = idx >> 4, c4 = idx & 15;
        float4 v = *reinterpret_cast<const float4*>(u + (size_t)s_batch[row] * 64 + c4 * 4);
        sts_h2(a_u32, row, 192 + 4 * c4,     v.x, v.y);
        sts_h2(a_u32, row, 192 + 4 * c4 + 2, v.z, v.w);
    }
    // re-zero this block's agg rows for the next graph replay
#pragma unroll
    for (int i = 0; i < 4; i++) {
        int idx = tid + i * THREADS;
        int row = idx >> 4, c4 = idx & 15;
        int gm = m0 + row;
        if (gm < N_NODES)
            *reinterpret_cast<float4*>(g_agg + (size_t)gm * 64 + c4 * 4) =
                make_float4(0.f, 0.f, 0.f, 0.f);
    }
    __syncthreads();  // h0 ready

    mlp_layer<256, true,  false>(a_u32, g_w1h, b1, nullptr, m0, wm, wn, g, t, lane);
    mlp_layer<256, true,  false>(a_u32, g_w2h, b2, nullptr, m0, wm, wn, g, t, lane);
    mlp_layer<128, false, true >(a_u32, g_w3h, b3, out,     m0, wm, wn, g, t, lane);
}

// ---------------- launch ----------------
extern "C" void kernel_launch(void* const* d_in, const int* in_sizes, int n_in,
                              void* d_out, int out_size) {
    const float* x          = (const float*)d_in[0];
    const int*   edge_index = (const int*)d_in[1];
    const float* edge_attr  = (const float*)d_in[2];
    const float* u          = (const float*)d_in[3];
    const int*   batch      = (const int*)d_in[4];
    const float* w1         = (const float*)d_in[5];
    const float* b1         = (const float*)d_in[6];
    const float* w2         = (const float*)d_in[7];
    const float* b2         = (const float*)d_in[8];
    const float* w3         = (const float*)d_in[9];
    const float* b3         = (const float*)d_in[10];
    float* out = (float*)d_out;

    const int SMEM_BYTES = BM * ASTR;  // 36864 B (A buffer only) -> 2 CTAs/SM (reg-capped)
    static bool attr_set = false;
    if (!attr_set) {
        cudaFuncSetAttribute(fused_mlp_kernel,
                             cudaFuncAttributeMaxDynamicSharedMemorySize, SMEM_BYTES);
        attr_set = true;
    }

    scatter_prep_kernel<<<SCAT_BLOCKS + 640, 256>>>(edge_attr, edge_index + N_EDGES,
                                                    w1, w2, w3);
    fused_mlp_kernel<<<(N_NODES + BM - 1) / BM, THREADS, SMEM_BYTES>>>(
        x, u, batch, b1, b2, b3, out);
}

// round 16
// speedup vs baseline: 1.0096x; 1.0096x over previous
#include <cuda_runtime.h>
#include <cuda_fp16.h>
#include <cstdint>

#define N_NODES  50000
#define N_EDGES  800000
#define BM       32
#define THREADS  256
#define ASTR     576     // A row stride bytes: 16B-aligned; /4=144 ≡16 mod 32 -> conflict-free LDS.128

// ---------------- device scratch (no allocs allowed; zero-initialized at load) ----
__device__ float  g_agg[N_NODES * 64];
__device__ __half g_w1h[256 * 256];
__device__ __half g_w2h[256 * 256];
__device__ __half g_w3h[256 * 128];

// ---------------- helpers ----------------
__device__ __forceinline__ void cp16(uint32_t smem_dst, const void* gsrc) {
    asm volatile("cp.async.cg.shared.global [%0], [%1], 16;" :: "r"(smem_dst), "l"(gsrc));
}
__device__ __forceinline__ uint4 lds128(uint32_t addr) {
    uint4 r;
    asm volatile("ld.shared.v4.b32 {%0,%1,%2,%3}, [%4];"
                 : "=r"(r.x), "=r"(r.y), "=r"(r.z), "=r"(r.w) : "r"(addr));
    return r;
}
__device__ __forceinline__ void mma_f16(float* c, uint32_t a0, uint32_t a1, uint32_t a2,
                                        uint32_t a3, uint32_t b0, uint32_t b1) {
    asm volatile(
        "mma.sync.aligned.m16n8k16.row.col.f32.f16.f16.f32 "
        "{%0,%1,%2,%3}, {%4,%5,%6,%7}, {%8,%9}, {%0,%1,%2,%3};"
        : "+f"(c[0]), "+f"(c[1]), "+f"(c[2]), "+f"(c[3])
        : "r"(a0), "r"(a1), "r"(a2), "r"(a3), "r"(b0), "r"(b1));
}
// store half2 into interleaved A layout at logical col c (even)
__device__ __forceinline__ void sts_h2(uint32_t a_u32, int row, int c, float f0, float f1) {
    int w = c & 31;
    int t = (w & 7) >> 1, s = (w >> 3) & 1, q = (w >> 4) & 1;
    uint32_t byte = (uint32_t)(row * ASTR + (c >> 5) * 64 + (8 * t + 4 * q + 2 * s) * 2);
    __half2 h = __floats2half2_rn(f0, f1);
    asm volatile("st.shared.b32 [%0], %1;" :: "r"(a_u32 + byte), "r"(*(uint32_t*)&h));
}

// ---------------- weight permute: per-fragment order, 8 n-slices of N/8 --------
// halves idx i: chunk(16 k-rows) -> wn slice (8 x N/8 cols) -> (p, lane, j8)
//   ni = 2p + (j8>>2); k = chunk*16 + 2t + 8*((j8>>1)&1) + (j8&1); n = wn*(N/8)+ni*8+g
__device__ __forceinline__ void permute_h(const float* __restrict__ W, __half* __restrict__ dst,
                                          int i, int N) {
    int chunk = i / (16 * N);
    int r = i - chunk * 16 * N;
    int sliceH = 2 * N;            // halves per (chunk, wn): 16 * (N/8)
    int wn = r / sliceH;
    int r2 = r - wn * sliceH;
    int p = r2 >> 8;
    int lane = (r2 >> 3) & 31;
    int j8 = r2 & 7;
    int g = lane >> 2, t = lane & 3;
    int ni = 2 * p + (j8 >> 2);
    int k = chunk * 16 + 2 * t + 8 * ((j8 >> 1) & 1) + (j8 & 1);
    int n = wn * (N >> 3) + ni * 8 + g;
    dst[i] = __float2half_rn(W[(size_t)k * N + n]);
}

// ---------------- scatter (warp-autonomous, pipelined within 32KB) + permute ---
#define SCAT_BLOCKS (N_EDGES / 128)   // 6250
__global__ __launch_bounds__(256) void scatter_prep_kernel(
    const float* __restrict__ edge_attr, const int* __restrict__ col,
    const float* __restrict__ w1, const float* __restrict__ w2,
    const float* __restrict__ w3) {
    int b = blockIdx.x;
    if (b < SCAT_BLOCKS) {
        __shared__ float se[128 * 64];   // 32KB
        const int tid = threadIdx.x, lane = tid & 31, warp = tid >> 5;
        const long e0 = (long)b * 128 + warp * 16;   // this warp's 16 edges
        const float* src = edge_attr + e0 * 64;
        const uint32_t sb = (uint32_t)__cvta_generic_to_shared(se) + warp * 4096;

        int mynode = (lane < 16) ? __ldg(col + e0 + lane) : 0;

        // stage group A: edges [0,8)
#pragma unroll
        for (int j = 0; j < 4; j++)
            cp16(sb + (j * 32 + lane) * 16, src + (j * 32 + lane) * 4);
        asm volatile("cp.async.commit_group;");
        // stage group B: edges [8,16)
#pragma unroll
        for (int j = 0; j < 4; j++)
            cp16(sb + 2048 + (j * 32 + lane) * 16, src + 512 + (j * 32 + lane) * 4);
        asm volatile("cp.async.commit_group;");

        const int eo = lane >> 1, half = lane & 1;
        int node_a = __shfl_sync(0xFFFFFFFF, mynode, eo);
        int node_b = __shfl_sync(0xFFFFFFFF, mynode, 8 + eo);

        asm volatile("cp.async.wait_group 1;");
        __syncwarp();
        asm volatile("fence.proxy.async.shared::cta;" ::: "memory");
        if (lane < 16) {
            asm volatile("cp.reduce.async.bulk.global.shared::cta.bulk_group.add.f32 [%0], [%1], %2;"
                         :: "l"(g_agg + (size_t)node_a * 64 + half * 32),
                            "r"(sb + eo * 256 + half * 128), "r"(128) : "memory");
        }
        asm volatile("cp.async.bulk.commit_group;");

        asm volatile("cp.async.wait_group 0;");
        __syncwarp();
        asm volatile("fence.proxy.async.shared::cta;" ::: "memory");
        if (lane < 16) {
            asm volatile("cp.reduce.async.bulk.global.shared::cta.bulk_group.add.f32 [%0], [%1], %2;"
                         :: "l"(g_agg + (size_t)node_b * 64 + half * 32),
                            "r"(sb + 2048 + eo * 256 + half * 128), "r"(128) : "memory");
        }
        asm volatile("cp.async.bulk.commit_group;");
        asm volatile("cp.async.bulk.wait_group 0;");
    } else {
        int i = (b - SCAT_BLOCKS) * 256 + threadIdx.x;   // 640 blocks -> 163840
        if (i < 65536)        permute_h(w1, g_w1h, i, 256);
        else if (i < 131072)  permute_h(w2, g_w2h, i - 65536, 256);
        else                  permute_h(w3, g_w3h, i - 131072, 128);
    }
}

// ---------------- fused MLP layer, fp16 m16n8k16, BM=32, 8 warps x (32x N/8) ----
// B fragments: direct gmem(L2)->register LDG.128 of this warp's private slice.
template <int N, bool RELU, bool TOGMEM>
__device__ __forceinline__ void mlp_layer(
    uint32_t a_u32, const __half* __restrict__ Wg,
    const float* __restrict__ bias, float* __restrict__ outg, int m0,
    int wn, int g, int t, int lane)
{
    constexpr int TW = N / 8;              // warp n-tile: 32 or 16
    constexpr int NI = N / 64;             // n8 tiles per warp: 4 or 2
    constexpr int NP = NI / 2;             // B LDG.128 per chunk: 2 or 1
    constexpr int CHUNK4 = 2 * N;          // uint4 per 16-k chunk (all warps)
    constexpr int SLICEH = 2 * N;          // halves per warp slice per chunk

    float acc[2][NI][4] = {};
    const uint4* wptr = reinterpret_cast<const uint4*>(Wg + wn * SLICEH + lane * 8);

    uint4 av[2][2];
    const uint32_t arow = a_u32 + (uint32_t)(g * ASTR + t * 16);

#pragma unroll
    for (int kt = 0; kt < 16; kt++) {
        uint4 bv[NP];
#pragma unroll
        for (int p = 0; p < NP; p++)
            bv[p] = __ldg(wptr + kt * CHUNK4 + p * 32);

        const int q = kt & 1;
        if (q == 0) {
#pragma unroll
            for (int mi = 0; mi < 2; mi++)
#pragma unroll
                for (int rh = 0; rh < 2; rh++)
                    av[mi][rh] = lds128(arow + (mi * 16 + rh * 8) * ASTR + (kt >> 1) * 64);
        }
        uint32_t a0[2], a1[2], a2[2], a3[2];
#pragma unroll
        for (int mi = 0; mi < 2; mi++) {
            a0[mi] = q ? av[mi][0].z : av[mi][0].x;
            a1[mi] = q ? av[mi][1].z : av[mi][1].x;
            a2[mi] = q ? av[mi][0].w : av[mi][0].y;
            a3[mi] = q ? av[mi][1].w : av[mi][1].y;
        }
#pragma unroll
        for (int p = 0; p < NP; p++) {
            mma_f16(acc[0][2 * p],     a0[0], a1[0], a2[0], a3[0], bv[p].x, bv[p].y);
            mma_f16(acc[1][2 * p],     a0[1], a1[1], a2[1], a3[1], bv[p].x, bv[p].y);
            mma_f16(acc[0][2 * p + 1], a0[0], a1[0], a2[0], a3[0], bv[p].z, bv[p].w);
            mma_f16(acc[1][2 * p + 1], a0[1], a1[1], a2[1], a3[1], bv[p].z, bv[p].w);
        }
    }
    __syncthreads();  // all warps done reading A before epilogue rewrites it

#pragma unroll
    for (int mi = 0; mi < 2; mi++) {
#pragma unroll
        for (int ni = 0; ni < NI; ni++) {
            int c = wn * TW + ni * 8 + 2 * t;
            float bv0 = bias[c], bv1 = bias[c + 1];
            float v0 = acc[mi][ni][0] + bv0;
            float v1 = acc[mi][ni][1] + bv1;
            float v2 = acc[mi][ni][2] + bv0;
            float v3 = acc[mi][ni][3] + bv1;
            if (RELU) {
                v0 = (v0 >= 0.f) ? v0 : 0.01f * v0;
                v1 = (v1 >= 0.f) ? v1 : 0.01f * v1;
                v2 = (v2 >= 0.f) ? v2 : 0.01f * v2;
                v3 = (v3 >= 0.f) ? v3 : 0.01f * v3;
            }
            int row = mi * 16 + g;
            if (TOGMEM) {
                int gm0 = m0 + row, gm1 = gm0 + 8;
                if (gm0 < N_NODES)
                    *reinterpret_cast<float2*>(outg + (size_t)gm0 * N + c) = make_float2(v0, v1);
                if (gm1 < N_NODES)
                    *reinterpret_cast<float2*>(outg + (size_t)gm1 * N + c) = make_float2(v2, v3);
            } else {
                sts_h2(a_u32, row,     c, v0, v1);
                sts_h2(a_u32, row + 8, c, v2, v3);
            }
        }
    }
    if (!TOGMEM) __syncthreads();
}

// ---------------- fused kernel: h0 build + re-zero agg + 3 layers --------------
__global__ __launch_bounds__(THREADS, 3) void fused_mlp_kernel(
    const float* __restrict__ x, const float* __restrict__ u,
    const int* __restrict__ batch,
    const float* __restrict__ b1, const float* __restrict__ b2,
    const float* __restrict__ b3, float* __restrict__ out) {
    extern __shared__ char smem_raw[];
    __shared__ int s_batch[BM];

    const int tid = threadIdx.x, lane = tid & 31, warp = tid >> 5;
    const int wn = warp;                 // 8 n-slices
    const int g = lane >> 2, t = lane & 3;
    const int m0 = blockIdx.x * BM;

    const uint32_t a_u32 = (uint32_t)__cvta_generic_to_shared(smem_raw);

    if (tid < BM) {
        int gm = m0 + tid;
        s_batch[tid] = (gm < N_NODES) ? batch[gm] : 0;
    }
    // h0 cols [0,128): x  (1024 float4)
#pragma unroll
    for (int i = 0; i < 4; i++) {
        int idx = tid + i * THREADS;
        int row = idx >> 5, c4 = idx & 31;
        int gm = m0 + row;
        float4 v = make_float4(0.f, 0.f, 0.f, 0.f);
        if (gm < N_NODES) v = *reinterpret_cast<const float4*>(x + (size_t)gm * 128 + c4 * 4);
        sts_h2(a_u32, row, 4 * c4,     v.x, v.y);
        sts_h2(a_u32, row, 4 * c4 + 2, v.z, v.w);
    }
    // h0 cols [128,192): agg  (512 float4)
#pragma unroll
    for (int i = 0; i < 2; i++) {
        int idx = tid + i * THREADS;
        int row = idx >> 4, c4 = idx & 15;
        int gm = m0 + row;
        float4 v = make_float4(0.f, 0.f, 0.f, 0.f);
        if (gm < N_NODES) v = *reinterpret_cast<const float4*>(g_agg + (size_t)gm * 64 + c4 * 4);
        sts_h2(a_u32, row, 128 + 4 * c4,     v.x, v.y);
        sts_h2(a_u32, row, 128 + 4 * c4 + 2, v.z, v.w);
    }
    __syncthreads();  // s_batch ready
    // h0 cols [192,256): u[batch]  (512 float4)
#pragma unroll
    for (int i = 0; i < 2; i++) {
        int idx = tid + i * THREADS;
        int row = idx >> 4, c4 = idx & 15;
        float4 v = *reinterpret_cast<const float4*>(u + (size_t)s_batch[row] * 64 + c4 * 4);
        sts_h2(a_u32, row, 192 + 4 * c4,     v.x, v.y);
        sts_h2(a_u32, row, 192 + 4 * c4 + 2, v.z, v.w);
    }
    // re-zero this block's agg rows for the next graph replay (512 float4)
#pragma unroll
    for (int i = 0; i < 2; i++) {
        int idx = tid + i * THREADS;
        int row = idx >> 4, c4 = idx & 15;
        int gm = m0 + row;
        if (gm < N_NODES)
            *reinterpret_cast<float4*>(g_agg + (size_t)gm * 64 + c4 * 4) =
                make_float4(0.f, 0.f, 0.f, 0.f);
    }
    __syncthreads();  // h0 ready

    mlp_layer<256, true,  false>(a_u32, g_w1h, b1, nullptr, m0, wn, g, t, lane);
    mlp_layer<256, true,  false>(a_u32, g_w2h, b2, nullptr, m0, wn, g, t, lane);
    mlp_layer<128, false, true >(a_u32, g_w3h, b3, out,     m0, wn, g, t, lane);
}

// ---------------- launch ----------------
extern "C" void kernel_launch(void* const* d_in, const int* in_sizes, int n_in,
                              void* d_out, int out_size) {
    const float* x          = (const float*)d_in[0];
    const int*   edge_index = (const int*)d_in[1];
    const float* edge_attr  = (const float*)d_in[2];
    const float* u          = (const float*)d_in[3];
    const int*   batch      = (const int*)d_in[4];
    const float* w1         = (const float*)d_in[5];
    const float* b1         = (const float*)d_in[6];
    const float* w2         = (const float*)d_in[7];
    const float* b2         = (const float*)d_in[8];
    const float* w3         = (const float*)d_in[9];
    const float* b3         = (const float*)d_in[10];
    float* out = (float*)d_out;

    const int SMEM_BYTES = BM * ASTR;  // 18432 B -> 3 CTAs/SM fits easily
    static bool attr_set = false;
    if (!attr_set) {
        cudaFuncSetAttribute(fused_mlp_kernel,
                             cudaFuncAttributeMaxDynamicSharedMemorySize, SMEM_BYTES);
        attr_set = true;
    }

    scatter_prep_kernel<<<SCAT_BLOCKS + 640, 256>>>(edge_attr, edge_index + N_EDGES,
                                                    w1, w2, w3);
    fused_mlp_kernel<<<(N_NODES + BM - 1) / BM, THREADS, SMEM_BYTES>>>(
        x, u, batch, b1, b2, b3, out);
}